// round 14
// baseline (speedup 1.0000x reference)
#include <cuda_runtime.h>
#include <math.h>

// Problem constants
constexpr int BSZ = 64;     // batch
constexpr int SEQ = 512;    // sequence length
constexpr int IN  = 512;    // input dim
constexpr int HD  = 1024;   // hidden dim
constexpr int G4  = 4 * HD; // 4096 gate columns

constexpr int NCTAS = 128;  // persistent grid (1 CTA per SM)
constexpr int NTHR  = 128;  // proven best: 1 warp per SMSP

constexpr int HBUF = BSZ * HD;   // one h buffer

// Scratch: xg = x @ Xcat + bcat, layout [m = b*SEQ + t][gate*HD + j]
__device__ float g_xg[(size_t)BSZ * SEQ * G4];   // 512 MB
__device__ float g_h[2 * HBUF];                  // double-buffered h (race-free)
__device__ unsigned g_count;
__device__ unsigned g_phase;

// Dynamic SMEM layout (bytes):
//   Bs: [1024][32] floats  @ 0        (131072 B)  -- Hcat slice, loaded once
//   As: [2][64][36] floats @ 131072   (18432 B)   -- double-buffered h chunks
//   Gs: [64][36] floats    @ 149504   (9216 B)    -- g tile for epilogue
constexpr int SMEM_BS    = 0;
constexpr int SMEM_AS    = 131072;
constexpr int SMEM_GS    = 149504;
constexpr int SMEM_TOTAL = 149504 + 9216;          // 158720 B

#define FMA2(acc, a, b) asm("fma.rn.f32x2 %0,%1,%2,%0;" : "+l"(acc) : "l"(a), "l"(b))

// Fast gate functions: __expf-based, saturate correctly at extremes.
__device__ __forceinline__ float fast_sigmoid(float x) {
    return __fdividef(1.0f, 1.0f + __expf(-x));
}
__device__ __forceinline__ float fast_tanh(float x) {
    // 1 - 2/(e^{2x}+1): x->+inf => exp->inf => 1; x->-inf => exp->0 => -1.
    return 1.0f - __fdividef(2.0f, __expf(2.0f * x) + 1.0f);
}

// ---------------------------------------------------------------------------
// Zero h buffers and barrier state
// ---------------------------------------------------------------------------
__global__ void init_state_kernel() {
    int i = blockIdx.x * blockDim.x + threadIdx.x;
    if (i < 2 * HBUF) g_h[i] = 0.0f;
    if (i == 0) { g_count = 0u; g_phase = 0u; }
}

// ---------------------------------------------------------------------------
// ncu alignment dummy: keeps the capture window on the persistent kernel.
// ---------------------------------------------------------------------------
__global__ void ncu_align_kernel() {}

// ---------------------------------------------------------------------------
// Input projection, FFMA2 (unchanged, proven)
// ---------------------------------------------------------------------------
__global__ __launch_bounds__(256, 4)
void xproj_kernel(const float* __restrict__ x,
                  const float* __restrict__ X1, const float* __restrict__ X2,
                  const float* __restrict__ X3, const float* __restrict__ X4,
                  const float* __restrict__ b1, const float* __restrict__ b2,
                  const float* __restrict__ b3, const float* __restrict__ b4)
{
    const int gate = blockIdx.z;
    const float* __restrict__ Xg = (gate == 0) ? X1 : (gate == 1) ? X2 : (gate == 2) ? X3 : X4;
    const float* __restrict__ bg = (gate == 0) ? b1 : (gate == 1) ? b2 : (gate == 2) ? b3 : b4;

    const int m0 = blockIdx.y * 64;
    const int n0 = blockIdx.x * 64;

    __shared__ float As[16][68];   // [k][m], padded stride 68
    __shared__ float Bs[16][64];   // [k][n]

    const int tid = threadIdx.x;
    const int tx = tid & 15;       // 4 n-cols each (2 f32x2 pairs)
    const int ty = tid >> 4;       // 4 m-rows each

    unsigned long long acc[4][2];
    #pragma unroll
    for (int r = 0; r < 4; r++) { acc[r][0] = 0ull; acc[r][1] = 0ull; }

    for (int k0 = 0; k0 < IN; k0 += 16) {
        {
            int row = tid >> 2;
            int kq  = tid & 3;
            float4 v = *(const float4*)(x + (size_t)(m0 + row) * IN + k0 + kq * 4);
            As[kq * 4 + 0][row] = v.x;
            As[kq * 4 + 1][row] = v.y;
            As[kq * 4 + 2][row] = v.z;
            As[kq * 4 + 3][row] = v.w;
        }
        {
            int kr = tid >> 4;
            int nq = tid & 15;
            float4 v = *(const float4*)(Xg + (size_t)(k0 + kr) * HD + n0 + nq * 4);
            *(float4*)&Bs[kr][nq * 4] = v;
        }
        __syncthreads();

        #pragma unroll
        for (int k = 0; k < 16; k++) {
            float4 a4 = *(const float4*)&As[k][ty * 4];
            ulonglong2 b = *(const ulonglong2*)&Bs[k][tx * 4];

            unsigned long long aa0, aa1, aa2, aa3;
            asm("mov.b64 %0,{%1,%1};" : "=l"(aa0) : "f"(a4.x));
            asm("mov.b64 %0,{%1,%1};" : "=l"(aa1) : "f"(a4.y));
            asm("mov.b64 %0,{%1,%1};" : "=l"(aa2) : "f"(a4.z));
            asm("mov.b64 %0,{%1,%1};" : "=l"(aa3) : "f"(a4.w));

            FMA2(acc[0][0], aa0, b.x); FMA2(acc[0][1], aa0, b.y);
            FMA2(acc[1][0], aa1, b.x); FMA2(acc[1][1], aa1, b.y);
            FMA2(acc[2][0], aa2, b.x); FMA2(acc[2][1], aa2, b.y);
            FMA2(acc[3][0], aa3, b.x); FMA2(acc[3][1], aa3, b.y);
        }
        __syncthreads();
    }

    #pragma unroll
    for (int r = 0; r < 4; r++) {
        int m = m0 + ty * 4 + r;
        size_t base = (size_t)m * G4 + (size_t)gate * HD + n0 + tx * 4;
        float f0, f1, f2, f3;
        asm("mov.b64 {%0,%1},%2;" : "=f"(f0), "=f"(f1) : "l"(acc[r][0]));
        asm("mov.b64 {%0,%1},%2;" : "=f"(f2), "=f"(f3) : "l"(acc[r][1]));
        g_xg[base + 0] = f0 + bg[n0 + tx * 4 + 0];
        g_xg[base + 1] = f1 + bg[n0 + tx * 4 + 1];
        g_xg[base + 2] = f2 + bg[n0 + tx * 4 + 2];
        g_xg[base + 3] = f3 + bg[n0 + tx * 4 + 3];
    }
}

// ---------------------------------------------------------------------------
// Software grid barrier (proven R12 version, unchanged)
// ---------------------------------------------------------------------------
__device__ __forceinline__ unsigned ld_cg_u32(const unsigned* p) {
    unsigned v;
    asm volatile("ld.global.cg.u32 %0,[%1];" : "=r"(v) : "l"(p));
    return v;
}

__device__ __forceinline__ void grid_sync(unsigned target) {
    __syncthreads();
    if (threadIdx.x == 0) {
        __threadfence();                      // publish h/out stores (required)
        if (atomicAdd(&g_count, 1u) == NCTAS - 1) {
            atomicExch(&g_count, 0u);
            __threadfence();
            atomicExch(&g_phase, target);
        } else {
            while (ld_cg_u32(&g_phase) < target) { __nanosleep(64); }
        }
        // no trailing fence: h reads are __ldcg (L2-direct), never stale L1
    }
    __syncthreads();
}

// ---------------------------------------------------------------------------
// Persistent recurrence kernel -- identical to the proven 13.98ms version
// EXCEPT: the inner-loop B loads are now plain C++ loads (no asm volatile),
// letting ptxas hoist/software-pipeline them like the A loads. Same SASS op
// (LDS.128), same addresses/banks, same values.
// ---------------------------------------------------------------------------
__global__ void __launch_bounds__(NTHR, 1)
lstm_persistent_kernel(const float* __restrict__ H1, const float* __restrict__ H2,
                       const float* __restrict__ H3, const float* __restrict__ H4,
                       float* __restrict__ out)
{
    extern __shared__ char smem[];
    float* Bs = (float*)(smem + SMEM_BS);   // [k][c], c = gate*8 + jj, stride 32
    float* As = (float*)(smem + SMEM_AS);   // [buf][row][kk], stride 36
    float* Gs = (float*)(smem + SMEM_GS);   // [row][col], stride 36

    const int tid = threadIdx.x;
    const int tx  = tid & 7;                // 4 tile-cols each
    const int ty  = tid >> 3;               // 0..15
    const int j0  = blockIdx.x * 8;

    // ---- Load Hcat slice (32 cols x 1024 k) into SMEM once ----
    {
        const int bk  = tid >> 2;           // 0..31
        const int bgt = tid & 3;            // gate
        const float* __restrict__ Hg = (bgt == 0) ? H1 : (bgt == 1) ? H2 : (bgt == 2) ? H3 : H4;
        for (int k0 = 0; k0 < HD; k0 += 32) {
            const float* src = Hg + (size_t)(k0 + bk) * HD + j0;
            float4 v0 = *(const float4*)(src);
            float4 v1 = *(const float4*)(src + 4);
            *(float4*)&Bs[(k0 + bk) * 32 + bgt * 8]     = v0;
            *(float4*)&Bs[(k0 + bk) * 32 + bgt * 8 + 4] = v1;
        }
    }

    // ---- Per-thread epilogue slots: 4 (b, j) pairs, fixed for all steps ----
    const float* xptr[4];
    int          hoff[4];                   // offset within an h buffer
    float*       optr[4];
    int          goff[4];                   // Gs base offset = b*36 + jj
    float        c_reg[4] = {0.f, 0.f, 0.f, 0.f};
    #pragma unroll
    for (int i = 0; i < 4; i++) {
        int p  = tid + NTHR * i;            // 0..511
        int b  = p >> 3;
        int jj = p & 7;
        int j  = j0 + jj;
        xptr[i] = g_xg + (size_t)b * SEQ * G4 + j;
        hoff[i] = b * HD + j;
        optr[i] = out + (size_t)b * SEQ * HD + j;
        goff[i] = b * 36 + jj;
    }

    // ---- A-staging slots: 4 float4 per thread per 64x32 chunk ----
    int aoff_g[4];                          // h-buffer float offset (row*HD + kq*4)
    int aoff_s[4];                          // As float offset (row*36 + kq*4)
    #pragma unroll
    for (int i = 0; i < 4; i++) {
        int q   = tid + NTHR * i;           // 0..511
        int row = q >> 3;                   // 0..63
        int kq  = q & 7;                    // 0..7
        aoff_g[i] = row * HD + kq * 4;
        aoff_s[i] = row * 36 + kq * 4;
    }

    __syncthreads();                        // Bs ready

    for (int t = 0; t < SEQ; t++) {
        const float* hrd = g_h + (size_t)(t & 1) * HBUF;          // h_{t-1}
        float*       hwr = g_h + (size_t)((t + 1) & 1) * HBUF;    // h_t

        // ---- Prefetch xg (DRAM) — hides under the K loop ----
        float xf[4], xi[4], xc[4], xo[4];
        const size_t toff = (size_t)t * G4;
        #pragma unroll
        for (int i = 0; i < 4; i++) {
            const float* xp = xptr[i] + toff;
            xf[i] = __ldg(xp);
            xi[i] = __ldg(xp + HD);
            xc[i] = __ldg(xp + 2 * HD);
            xo[i] = __ldg(xp + 3 * HD);
        }

        unsigned long long acc0[4] = {0ull, 0ull, 0ull, 0ull};  // cols tx*4+0,1
        unsigned long long acc1[4] = {0ull, 0ull, 0ull, 0ull};  // cols tx*4+2,3

        // ---- Prologue: stage chunk 0, prefetch chunk 1 (L2-direct) ----
        float4 v[4];
        #pragma unroll
        for (int i = 0; i < 4; i++) v[i] = __ldcg((const float4*)(hrd + aoff_g[i]));
        #pragma unroll
        for (int i = 0; i < 4; i++) *(float4*)&As[aoff_s[i]] = v[i];
        #pragma unroll
        for (int i = 0; i < 4; i++) v[i] = __ldcg((const float4*)(hrd + aoff_g[i] + 32));
        __syncthreads();

        for (int ch = 0; ch < 32; ch++) {
            // Stage chunk ch+1 into the other buffer
            if (ch + 1 < 32) {
                const int nb = ((ch + 1) & 1) * 2304;
                #pragma unroll
                for (int i = 0; i < 4; i++) *(float4*)&As[nb + aoff_s[i]] = v[i];
            }
            // Prefetch chunk ch+2 from global (L2-direct)
            if (ch + 2 < 32) {
                const int gk = (ch + 2) * 32;
                #pragma unroll
                for (int i = 0; i < 4; i++)
                    v[i] = __ldcg((const float4*)(hrd + aoff_g[i] + gk));
            }

            const float* Ab = As + (ch & 1) * 2304;
            const float* Bb = Bs + ch * 1024 + tx * 4;

            #pragma unroll
            for (int k4 = 0; k4 < 8; k4++) {
                float a0v[4], a1v[4], a2v[4], a3v[4];
                *(float4*)a0v = *(const float4*)&Ab[(ty +  0) * 36 + k4 * 4];
                *(float4*)a1v = *(const float4*)&Ab[(ty + 16) * 36 + k4 * 4];
                *(float4*)a2v = *(const float4*)&Ab[(ty + 32) * 36 + k4 * 4];
                *(float4*)a3v = *(const float4*)&Ab[(ty + 48) * 36 + k4 * 4];

                #pragma unroll
                for (int e = 0; e < 4; e++) {
                    // Plain (non-volatile) B load: LDS.128, freely schedulable
                    ulonglong2 bb = *(const ulonglong2*)(Bb + (k4 * 4 + e) * 32);

                    unsigned long long aa0, aa1, aa2, aa3;
                    asm("mov.b64 %0,{%1,%1};" : "=l"(aa0) : "f"(a0v[e]));
                    asm("mov.b64 %0,{%1,%1};" : "=l"(aa1) : "f"(a1v[e]));
                    asm("mov.b64 %0,{%1,%1};" : "=l"(aa2) : "f"(a2v[e]));
                    asm("mov.b64 %0,{%1,%1};" : "=l"(aa3) : "f"(a3v[e]));

                    FMA2(acc0[0], aa0, bb.x); FMA2(acc1[0], aa0, bb.y);
                    FMA2(acc0[1], aa1, bb.x); FMA2(acc1[1], aa1, bb.y);
                    FMA2(acc0[2], aa2, bb.x); FMA2(acc1[2], aa2, bb.y);
                    FMA2(acc0[3], aa3, bb.x); FMA2(acc1[3], aa3, bb.y);
                }
            }
            __syncthreads();
        }

        // ---- Stage g tile into Gs (rows ty + 16r) ----
        #pragma unroll
        for (int r = 0; r < 4; r++) {
            float f0, f1, f2, f3;
            asm("mov.b64 {%0,%1},%2;" : "=f"(f0), "=f"(f1) : "l"(acc0[r]));
            asm("mov.b64 {%0,%1},%2;" : "=f"(f2), "=f"(f3) : "l"(acc1[r]));
            float4 g4v = make_float4(f0, f1, f2, f3);
            *(float4*)&Gs[(ty + 16 * r) * 36 + tx * 4] = g4v;
        }
        __syncthreads();

        // ---- Epilogue: fast-math gates, c/h update, output ----
        #pragma unroll
        for (int i = 0; i < 4; i++) {
            const int go_ = goff[i];
            float gf = Gs[go_ +  0] + xf[i];
            float gi = Gs[go_ +  8] + xi[i];
            float gc = Gs[go_ + 16] + xc[i];
            float gg = Gs[go_ + 24] + xo[i];

            float s1 = fast_sigmoid(gf);
            float s2 = fast_sigmoid(gi);
            float t1 = fast_tanh(gc);
            float s3 = fast_sigmoid(gg);

            c_reg[i] = c_reg[i] * s1 + s2 * t1;
            float hnew = fast_tanh(c_reg[i]) * s3;

            hwr[hoff[i]] = hnew;
            optr[i][(size_t)t * HD] = hnew;
        }

        // ---- Grid-wide barrier before next step reads updated h ----
        if (t + 1 < SEQ) grid_sync((unsigned)(t + 1));
    }
}

// ---------------------------------------------------------------------------
// Launch
// ---------------------------------------------------------------------------
extern "C" void kernel_launch(void* const* d_in, const int* in_sizes, int n_in,
                              void* d_out, int out_size)
{
    const float* x  = (const float*)d_in[0];
    const float* X1 = (const float*)d_in[1];
    const float* H1 = (const float*)d_in[2];
    const float* b1 = (const float*)d_in[3];
    const float* X2 = (const float*)d_in[4];
    const float* H2 = (const float*)d_in[5];
    const float* b2 = (const float*)d_in[6];
    const float* X3 = (const float*)d_in[7];
    const float* H3 = (const float*)d_in[8];
    const float* b3 = (const float*)d_in[9];
    const float* X4 = (const float*)d_in[10];
    const float* H4 = (const float*)d_in[11];
    const float* b4 = (const float*)d_in[12];
    float* out = (float*)d_out;

    cudaFuncSetAttribute(lstm_persistent_kernel,
                         cudaFuncAttributeMaxDynamicSharedMemorySize, SMEM_TOTAL);

    // Zero recurrent state (both buffers) + barrier
    init_state_kernel<<<(2 * HBUF + 255) / 256, 256>>>();

    // Input projection: xg = x @ Xcat + bcat (FFMA2 GEMM)
    dim3 grid_x(HD / 64, (BSZ * SEQ) / 64, 4);
    xproj_kernel<<<grid_x, 256>>>(x, X1, X2, X3, X4, b1, b2, b3, b4);

    // ncu alignment: keep capture window on the persistent kernel
    ncu_align_kernel<<<1, 1>>>();

    // Persistent recurrence: all 512 steps in one kernel
    lstm_persistent_kernel<<<NCTAS, NTHR, SMEM_TOTAL>>>(H1, H2, H3, H4, out);
}

// round 15
// speedup vs baseline: 1.0558x; 1.0558x over previous
#include <cuda_runtime.h>
#include <math.h>

// Problem constants
constexpr int BSZ = 64;     // batch
constexpr int SEQ = 512;    // sequence length
constexpr int IN  = 512;    // input dim
constexpr int HD  = 1024;   // hidden dim
constexpr int G4  = 4 * HD; // 4096 gate columns

constexpr int NCTAS = 128;  // persistent grid (1 CTA per SM)
constexpr int NTHR  = 256;  // 8 warps: K-split halves (warps 0-3: K lo, 4-7: K hi)

constexpr int HBUF = BSZ * HD;   // one h buffer

// Scratch: xg = x @ Xcat + bcat, layout [m = b*SEQ + t][gate*HD + j]
__device__ float g_xg[(size_t)BSZ * SEQ * G4];   // 512 MB
__device__ float g_h[2 * HBUF];                  // double-buffered h (race-free)
__device__ unsigned g_count;
__device__ unsigned g_phase;

// Dynamic SMEM layout (bytes):
//   Bs:  [1024][32] floats          @ 0       (131072 B) -- Hcat slice, loaded once
//   As:  [half][buf][64][36] floats @ 131072  (36864 B)  -- per-half double-buffered h
//   Gs:  [64][36] floats            @ 167936  (9216 B)   -- half-0 partial g
//   Gs2: [64][36] floats            @ 177152  (9216 B)   -- half-1 partial g
constexpr int SMEM_BS    = 0;
constexpr int SMEM_AS    = 131072;
constexpr int AS_HALF    = 2 * 2304;      // floats per half (2 bufs x 64 x 36)
constexpr int SMEM_GS    = 167936;
constexpr int SMEM_GS2   = 177152;
constexpr int SMEM_TOTAL = 177152 + 9216;  // 186368 B

#define FMA2(acc, a, b) asm("fma.rn.f32x2 %0,%1,%2,%0;" : "+l"(acc) : "l"(a), "l"(b))

// Fast gate functions: __expf-based, saturate correctly at extremes.
__device__ __forceinline__ float fast_sigmoid(float x) {
    return __fdividef(1.0f, 1.0f + __expf(-x));
}
__device__ __forceinline__ float fast_tanh(float x) {
    return 1.0f - __fdividef(2.0f, __expf(2.0f * x) + 1.0f);
}

// ---------------------------------------------------------------------------
// Zero h buffers and barrier state
// ---------------------------------------------------------------------------
__global__ void init_state_kernel() {
    int i = blockIdx.x * blockDim.x + threadIdx.x;
    if (i < 2 * HBUF) g_h[i] = 0.0f;
    if (i == 0) { g_count = 0u; g_phase = 0u; }
}

// ---------------------------------------------------------------------------
// ncu alignment dummy: keeps the capture window on the persistent kernel.
// ---------------------------------------------------------------------------
__global__ void ncu_align_kernel() {}

// ---------------------------------------------------------------------------
// Input projection, FFMA2 (unchanged, proven)
// ---------------------------------------------------------------------------
__global__ __launch_bounds__(256, 4)
void xproj_kernel(const float* __restrict__ x,
                  const float* __restrict__ X1, const float* __restrict__ X2,
                  const float* __restrict__ X3, const float* __restrict__ X4,
                  const float* __restrict__ b1, const float* __restrict__ b2,
                  const float* __restrict__ b3, const float* __restrict__ b4)
{
    const int gate = blockIdx.z;
    const float* __restrict__ Xg = (gate == 0) ? X1 : (gate == 1) ? X2 : (gate == 2) ? X3 : X4;
    const float* __restrict__ bg = (gate == 0) ? b1 : (gate == 1) ? b2 : (gate == 2) ? b3 : b4;

    const int m0 = blockIdx.y * 64;
    const int n0 = blockIdx.x * 64;

    __shared__ float As[16][68];   // [k][m], padded stride 68
    __shared__ float Bs[16][64];   // [k][n]

    const int tid = threadIdx.x;
    const int tx = tid & 15;       // 4 n-cols each (2 f32x2 pairs)
    const int ty = tid >> 4;       // 4 m-rows each

    unsigned long long acc[4][2];
    #pragma unroll
    for (int r = 0; r < 4; r++) { acc[r][0] = 0ull; acc[r][1] = 0ull; }

    for (int k0 = 0; k0 < IN; k0 += 16) {
        {
            int row = tid >> 2;
            int kq  = tid & 3;
            float4 v = *(const float4*)(x + (size_t)(m0 + row) * IN + k0 + kq * 4);
            As[kq * 4 + 0][row] = v.x;
            As[kq * 4 + 1][row] = v.y;
            As[kq * 4 + 2][row] = v.z;
            As[kq * 4 + 3][row] = v.w;
        }
        {
            int kr = tid >> 4;
            int nq = tid & 15;
            float4 v = *(const float4*)(Xg + (size_t)(k0 + kr) * HD + n0 + nq * 4);
            *(float4*)&Bs[kr][nq * 4] = v;
        }
        __syncthreads();

        #pragma unroll
        for (int k = 0; k < 16; k++) {
            float4 a4 = *(const float4*)&As[k][ty * 4];
            ulonglong2 b = *(const ulonglong2*)&Bs[k][tx * 4];

            unsigned long long aa0, aa1, aa2, aa3;
            asm("mov.b64 %0,{%1,%1};" : "=l"(aa0) : "f"(a4.x));
            asm("mov.b64 %0,{%1,%1};" : "=l"(aa1) : "f"(a4.y));
            asm("mov.b64 %0,{%1,%1};" : "=l"(aa2) : "f"(a4.z));
            asm("mov.b64 %0,{%1,%1};" : "=l"(aa3) : "f"(a4.w));

            FMA2(acc[0][0], aa0, b.x); FMA2(acc[0][1], aa0, b.y);
            FMA2(acc[1][0], aa1, b.x); FMA2(acc[1][1], aa1, b.y);
            FMA2(acc[2][0], aa2, b.x); FMA2(acc[2][1], aa2, b.y);
            FMA2(acc[3][0], aa3, b.x); FMA2(acc[3][1], aa3, b.y);
        }
        __syncthreads();
    }

    #pragma unroll
    for (int r = 0; r < 4; r++) {
        int m = m0 + ty * 4 + r;
        size_t base = (size_t)m * G4 + (size_t)gate * HD + n0 + tx * 4;
        float f0, f1, f2, f3;
        asm("mov.b64 {%0,%1},%2;" : "=f"(f0), "=f"(f1) : "l"(acc[r][0]));
        asm("mov.b64 {%0,%1},%2;" : "=f"(f2), "=f"(f3) : "l"(acc[r][1]));
        g_xg[base + 0] = f0 + bg[n0 + tx * 4 + 0];
        g_xg[base + 1] = f1 + bg[n0 + tx * 4 + 1];
        g_xg[base + 2] = f2 + bg[n0 + tx * 4 + 2];
        g_xg[base + 3] = f3 + bg[n0 + tx * 4 + 3];
    }
}

// ---------------------------------------------------------------------------
// Software grid barrier (proven R12 version, unchanged)
// ---------------------------------------------------------------------------
__device__ __forceinline__ unsigned ld_cg_u32(const unsigned* p) {
    unsigned v;
    asm volatile("ld.global.cg.u32 %0,[%1];" : "=r"(v) : "l"(p));
    return v;
}

__device__ __forceinline__ void grid_sync(unsigned target) {
    __syncthreads();
    if (threadIdx.x == 0) {
        __threadfence();                      // publish h/out stores (required)
        if (atomicAdd(&g_count, 1u) == NCTAS - 1) {
            atomicExch(&g_count, 0u);
            __threadfence();
            atomicExch(&g_phase, target);
        } else {
            while (ld_cg_u32(&g_phase) < target) { __nanosleep(64); }
        }
        // no trailing fence: h reads are __ldcg (L2-direct), never stale L1
    }
    __syncthreads();
}

// ---------------------------------------------------------------------------
// Persistent recurrence kernel, K-SPLIT across two warp halves:
//   warps 0-3 accumulate K in [0,512), warps 4-7 K in [512,1024) for the SAME
//   64x32 output tile. Total LDS/LDG traffic per SM is unchanged vs the
//   proven kernel (no replication); per-warp instruction count halves, and
//   2 warps/SMSP interleave to hide LDS latency. Partials combine via Gs+Gs2.
// Inner-loop shape (A rows ty+16r via conflict-free LDS.128, broadcast B,
// FFMA2) is identical to the proven 13.98ms kernel.
// ---------------------------------------------------------------------------
__global__ void __launch_bounds__(NTHR, 1)
lstm_persistent_kernel(const float* __restrict__ H1, const float* __restrict__ H2,
                       const float* __restrict__ H3, const float* __restrict__ H4,
                       float* __restrict__ out)
{
    extern __shared__ char smem[];
    float* Bs  = (float*)(smem + SMEM_BS);   // [k][c], c = gate*8 + jj, stride 32
    float* As  = (float*)(smem + SMEM_AS);   // [half][buf][row][kk], stride 36
    float* Gs  = (float*)(smem + SMEM_GS);   // half-0 partial g [row][col], stride 36
    float* Gs2 = (float*)(smem + SMEM_GS2);  // half-1 partial g

    const int tid   = threadIdx.x;
    const int half  = tid >> 7;              // 0: K[0,512), 1: K[512,1024)
    const int hid   = tid & 127;             // id within half
    const int tx    = hid & 7;               // 4 tile-cols each
    const int ty    = hid >> 3;              // 0..15
    const int j0    = blockIdx.x * 8;
    const int kbase = half * 512;            // K range start for this half

    float* Ah  = As + half * AS_HALF;        // this half's double-buffered region
    float* Gmy = half ? Gs2 : Gs;            // this half's partial output

    // ---- Load Hcat slice (32 cols x 1024 k) into SMEM once (256 threads) ----
    {
        const int bk  = (tid >> 2) & 63;    // 0..63 k-rows per pass
        const int bgt = tid & 3;            // gate
        const float* __restrict__ Hg = (bgt == 0) ? H1 : (bgt == 1) ? H2 : (bgt == 2) ? H3 : H4;
        for (int k0 = 0; k0 < HD; k0 += 64) {
            const float* src = Hg + (size_t)(k0 + bk) * HD + j0;
            float4 v0 = *(const float4*)(src);
            float4 v1 = *(const float4*)(src + 4);
            *(float4*)&Bs[(k0 + bk) * 32 + bgt * 8]     = v0;
            *(float4*)&Bs[(k0 + bk) * 32 + bgt * 8 + 4] = v1;
        }
    }

    // ---- Per-thread epilogue slots: 2 (b, j) pairs (256 threads x 2 = 512) ----
    const float* xptr[2];
    int          hoff[2];
    float*       optr[2];
    int          goff[2];
    float        c_reg[2] = {0.f, 0.f};
    #pragma unroll
    for (int i = 0; i < 2; i++) {
        int p  = tid + NTHR * i;            // 0..511
        int b  = p >> 3;
        int jj = p & 7;
        int j  = j0 + jj;
        xptr[i] = g_xg + (size_t)b * SEQ * G4 + j;
        hoff[i] = b * HD + j;
        optr[i] = out + (size_t)b * SEQ * HD + j;
        goff[i] = b * 36 + jj;
    }

    // ---- A-staging slots: 4 float4 per thread per 64x32 chunk (per half) ----
    int aoff_g[4];                          // h-buffer offset (row*HD + kbase + kq*4)
    int aoff_s[4];                          // As offset within half (row*36 + kq*4)
    #pragma unroll
    for (int i = 0; i < 4; i++) {
        int q   = hid + 128 * i;            // 0..511
        int row = q >> 3;                   // 0..63
        int kq  = q & 7;                    // 0..7
        aoff_g[i] = row * HD + kbase + kq * 4;
        aoff_s[i] = row * 36 + kq * 4;
    }

    __syncthreads();                        // Bs ready

    for (int t = 0; t < SEQ; t++) {
        const float* hrd = g_h + (size_t)(t & 1) * HBUF;          // h_{t-1}
        float*       hwr = g_h + (size_t)((t + 1) & 1) * HBUF;    // h_t

        // ---- Prefetch xg (DRAM) — hides under the K loop ----
        float xf[2], xi[2], xc[2], xo[2];
        const size_t toff = (size_t)t * G4;
        #pragma unroll
        for (int i = 0; i < 2; i++) {
            const float* xp = xptr[i] + toff;
            xf[i] = __ldg(xp);
            xi[i] = __ldg(xp + HD);
            xc[i] = __ldg(xp + 2 * HD);
            xo[i] = __ldg(xp + 3 * HD);
        }

        unsigned long long acc0[4] = {0ull, 0ull, 0ull, 0ull};  // cols tx*4+0,1
        unsigned long long acc1[4] = {0ull, 0ull, 0ull, 0ull};  // cols tx*4+2,3

        // ---- Prologue: stage chunk 0 of this half, prefetch chunk 1 ----
        float4 v[4];
        #pragma unroll
        for (int i = 0; i < 4; i++) v[i] = __ldcg((const float4*)(hrd + aoff_g[i]));
        #pragma unroll
        for (int i = 0; i < 4; i++) *(float4*)&Ah[aoff_s[i]] = v[i];
        #pragma unroll
        for (int i = 0; i < 4; i++) v[i] = __ldcg((const float4*)(hrd + aoff_g[i] + 32));
        __syncthreads();

        // 16 chunks of 32 k per half
        for (int ch = 0; ch < 16; ch++) {
            if (ch + 1 < 16) {
                const int nb = ((ch + 1) & 1) * 2304;
                #pragma unroll
                for (int i = 0; i < 4; i++) *(float4*)&Ah[nb + aoff_s[i]] = v[i];
            }
            if (ch + 2 < 16) {
                const int gk = (ch + 2) * 32;
                #pragma unroll
                for (int i = 0; i < 4; i++)
                    v[i] = __ldcg((const float4*)(hrd + aoff_g[i] + gk));
            }

            const float* Ab = Ah + (ch & 1) * 2304;
            const float* Bb = Bs + (kbase + ch * 32) * 32 + tx * 4;

            #pragma unroll
            for (int k4 = 0; k4 < 8; k4++) {
                float a0v[4], a1v[4], a2v[4], a3v[4];
                *(float4*)a0v = *(const float4*)&Ab[(ty +  0) * 36 + k4 * 4];
                *(float4*)a1v = *(const float4*)&Ab[(ty + 16) * 36 + k4 * 4];
                *(float4*)a2v = *(const float4*)&Ab[(ty + 32) * 36 + k4 * 4];
                *(float4*)a3v = *(const float4*)&Ab[(ty + 48) * 36 + k4 * 4];

                #pragma unroll
                for (int e = 0; e < 4; e++) {
                    ulonglong2 bb = *(const ulonglong2*)(Bb + (k4 * 4 + e) * 32);

                    unsigned long long aa0, aa1, aa2, aa3;
                    asm("mov.b64 %0,{%1,%1};" : "=l"(aa0) : "f"(a0v[e]));
                    asm("mov.b64 %0,{%1,%1};" : "=l"(aa1) : "f"(a1v[e]));
                    asm("mov.b64 %0,{%1,%1};" : "=l"(aa2) : "f"(a2v[e]));
                    asm("mov.b64 %0,{%1,%1};" : "=l"(aa3) : "f"(a3v[e]));

                    FMA2(acc0[0], aa0, bb.x); FMA2(acc1[0], aa0, bb.y);
                    FMA2(acc0[1], aa1, bb.x); FMA2(acc1[1], aa1, bb.y);
                    FMA2(acc0[2], aa2, bb.x); FMA2(acc1[2], aa2, bb.y);
                    FMA2(acc0[3], aa3, bb.x); FMA2(acc1[3], aa3, bb.y);
                }
            }
            __syncthreads();
        }

        // ---- Stage partial g tiles: half 0 -> Gs, half 1 -> Gs2 ----
        #pragma unroll
        for (int r = 0; r < 4; r++) {
            float f0, f1, f2, f3;
            asm("mov.b64 {%0,%1},%2;" : "=f"(f0), "=f"(f1) : "l"(acc0[r]));
            asm("mov.b64 {%0,%1},%2;" : "=f"(f2), "=f"(f3) : "l"(acc1[r]));
            float4 g4v = make_float4(f0, f1, f2, f3);
            *(float4*)&Gmy[(ty + 16 * r) * 36 + tx * 4] = g4v;
        }
        __syncthreads();

        // ---- Epilogue: combine partials, fast-math gates, c/h update ----
        #pragma unroll
        for (int i = 0; i < 2; i++) {
            const int go_ = goff[i];
            float gf = Gs[go_ +  0] + Gs2[go_ +  0] + xf[i];
            float gi = Gs[go_ +  8] + Gs2[go_ +  8] + xi[i];
            float gc = Gs[go_ + 16] + Gs2[go_ + 16] + xc[i];
            float gg = Gs[go_ + 24] + Gs2[go_ + 24] + xo[i];

            float s1 = fast_sigmoid(gf);
            float s2 = fast_sigmoid(gi);
            float t1 = fast_tanh(gc);
            float s3 = fast_sigmoid(gg);

            c_reg[i] = c_reg[i] * s1 + s2 * t1;
            float hnew = fast_tanh(c_reg[i]) * s3;

            hwr[hoff[i]] = hnew;
            optr[i][(size_t)t * HD] = hnew;
        }

        // ---- Grid-wide barrier before next step reads updated h ----
        if (t + 1 < SEQ) grid_sync((unsigned)(t + 1));
    }
}

// ---------------------------------------------------------------------------
// Launch
// ---------------------------------------------------------------------------
extern "C" void kernel_launch(void* const* d_in, const int* in_sizes, int n_in,
                              void* d_out, int out_size)
{
    const float* x  = (const float*)d_in[0];
    const float* X1 = (const float*)d_in[1];
    const float* H1 = (const float*)d_in[2];
    const float* b1 = (const float*)d_in[3];
    const float* X2 = (const float*)d_in[4];
    const float* H2 = (const float*)d_in[5];
    const float* b2 = (const float*)d_in[6];
    const float* X3 = (const float*)d_in[7];
    const float* H3 = (const float*)d_in[8];
    const float* b3 = (const float*)d_in[9];
    const float* X4 = (const float*)d_in[10];
    const float* H4 = (const float*)d_in[11];
    const float* b4 = (const float*)d_in[12];
    float* out = (float*)d_out;

    cudaFuncSetAttribute(lstm_persistent_kernel,
                         cudaFuncAttributeMaxDynamicSharedMemorySize, SMEM_TOTAL);

    // Zero recurrent state (both buffers) + barrier
    init_state_kernel<<<(2 * HBUF + 255) / 256, 256>>>();

    // Input projection: xg = x @ Xcat + bcat (FFMA2 GEMM)
    dim3 grid_x(HD / 64, (BSZ * SEQ) / 64, 4);
    xproj_kernel<<<grid_x, 256>>>(x, X1, X2, X3, X4, b1, b2, b3, b4);

    // ncu alignment: keep capture window on the persistent kernel
    ncu_align_kernel<<<1, 1>>>();

    // Persistent recurrence: all 512 steps in one kernel
    lstm_persistent_kernel<<<NCTAS, NTHR, SMEM_TOTAL>>>(H1, H2, H3, H4, out);
}